// round 1
// baseline (speedup 1.0000x reference)
#include <cuda_runtime.h>
#include <cuda_bf16.h>
#include <cstdint>

#define NTOK     8192
#define DM       2048
#define DH       2048
#define NEXP     8
#define TOPK     2
#define TASSIGN  (NTOK * TOPK)     // 16384
#define CAP      2560              // int(1.25 * 2 * 8192 / 8)

#define BM 128
#define BN 64
#define BK 16

// -------- scratch (device globals; no allocs allowed) --------
__device__ int   g_counts[NEXP];
__device__ int   g_tok_of_slot[NEXP * CAP];
__device__ int   g_slot_of_assign[TASSIGN];
__device__ float g_h[(size_t)NEXP * CAP * DH];   // ~168 MB
__device__ float g_y[(size_t)NEXP * CAP * DM];   // ~168 MB

// ---------------- routing: stable ranks via warp ballot ----------------
__global__ void route_kernel(const int* __restrict__ idx) {
    int w    = threadIdx.x >> 5;   // expert this warp owns
    int lane = threadIdx.x & 31;
    if (w >= NEXP) return;
    int base = 0;
    for (int t0 = 0; t0 < TASSIGN; t0 += 32) {
        int t = t0 + lane;
        int e = idx[t];
        bool m = (e == w);
        unsigned mask = __ballot_sync(0xffffffffu, m);
        if (m) {
            int rank = base + __popc(mask & ((1u << lane) - 1u));
            int slot = -1;
            if (rank < CAP) {
                slot = w * CAP + rank;
                g_tok_of_slot[slot] = t / TOPK;
            }
            g_slot_of_assign[t] = slot;
        }
        base += __popc(mask);
    }
    if (lane == 0) g_counts[w] = base;   // full histogram (uncapped), matches reference
}

// ---------------- GEMM1 fused: h = silu(x@w1) * (x@w3) ----------------
__global__ __launch_bounds__(256) void gemm1_kernel(const float* __restrict__ x,
                                                    const float* __restrict__ w1,
                                                    const float* __restrict__ w3) {
    const int e   = blockIdx.z;
    int cnt = g_counts[e];
    if (cnt > CAP) cnt = CAP;
    const int m0 = blockIdx.y * BM;
    if (m0 >= cnt) return;
    const int n0 = blockIdx.x * BN;

    __shared__ float As[BK][BM + 4];
    __shared__ float Bs1[BK][BN];
    __shared__ float Bs3[BK][BN];

    const int tid = threadIdx.x;
    const int tx  = tid & 15;   // n dir (16 * 4 = 64)
    const int ty  = tid >> 4;   // m dir (16 * 8 = 128)

    // A load mapping: 128 rows x 16 cols = 512 float4; 2 per thread
    const int rowA = tid >> 2;          // 0..63
    const int cA   = (tid & 3) * 4;     // 0,4,8,12

    const float* xrow0 = nullptr;
    const float* xrow1 = nullptr;
    {
        int r0 = m0 + rowA;
        if (r0 < cnt) xrow0 = x + (size_t)g_tok_of_slot[e * CAP + r0] * DM;
        int r1 = m0 + rowA + 64;
        if (r1 < cnt) xrow1 = x + (size_t)g_tok_of_slot[e * CAP + r1] * DM;
    }

    // B load mapping: 16 x 64 = 256 float4; 1 per thread
    const int kB = tid >> 4;            // 0..15
    const int nB = (tid & 15) * 4;      // 0..60
    const float* pB1 = w1 + (size_t)e * DM * DH + (size_t)kB * DH + n0 + nB;
    const float* pB3 = w3 + (size_t)e * DM * DH + (size_t)kB * DH + n0 + nB;

    float acc1[8][4], acc3[8][4];
#pragma unroll
    for (int i = 0; i < 8; i++)
#pragma unroll
        for (int j = 0; j < 4; j++) { acc1[i][j] = 0.f; acc3[i][j] = 0.f; }

    for (int k0 = 0; k0 < DM; k0 += BK) {
        float4 a0 = xrow0 ? *(const float4*)(xrow0 + k0 + cA) : make_float4(0.f, 0.f, 0.f, 0.f);
        float4 a1 = xrow1 ? *(const float4*)(xrow1 + k0 + cA) : make_float4(0.f, 0.f, 0.f, 0.f);
        float4 b1 = *(const float4*)(pB1 + (size_t)k0 * DH);
        float4 b3 = *(const float4*)(pB3 + (size_t)k0 * DH);

        As[cA + 0][rowA] = a0.x;  As[cA + 1][rowA] = a0.y;
        As[cA + 2][rowA] = a0.z;  As[cA + 3][rowA] = a0.w;
        As[cA + 0][rowA + 64] = a1.x;  As[cA + 1][rowA + 64] = a1.y;
        As[cA + 2][rowA + 64] = a1.z;  As[cA + 3][rowA + 64] = a1.w;
        *(float4*)&Bs1[kB][nB] = b1;
        *(float4*)&Bs3[kB][nB] = b3;
        __syncthreads();

#pragma unroll
        for (int k = 0; k < BK; k++) {
            float a[8], bv1[4], bv3[4];
#pragma unroll
            for (int i = 0; i < 8; i++) a[i] = As[k][ty * 8 + i];
#pragma unroll
            for (int j = 0; j < 4; j++) { bv1[j] = Bs1[k][tx * 4 + j]; bv3[j] = Bs3[k][tx * 4 + j]; }
#pragma unroll
            for (int i = 0; i < 8; i++)
#pragma unroll
                for (int j = 0; j < 4; j++) {
                    acc1[i][j] = fmaf(a[i], bv1[j], acc1[i][j]);
                    acc3[i][j] = fmaf(a[i], bv3[j], acc3[i][j]);
                }
        }
        __syncthreads();
    }

    // epilogue: h = silu(acc1) * acc3
#pragma unroll
    for (int i = 0; i < 8; i++) {
        int r = m0 + ty * 8 + i;
        if (r >= cnt) continue;
        float* hp = g_h + (size_t)(e * CAP + r) * DH + n0 + tx * 4;
#pragma unroll
        for (int j = 0; j < 4; j++) {
            float v = acc1[i][j];
            float s = v / (1.f + __expf(-v));
            hp[j] = s * acc3[i][j];
        }
    }
}

// ---------------- GEMM2: y = h @ w2 ----------------
__global__ __launch_bounds__(256) void gemm2_kernel(const float* __restrict__ w2) {
    const int e   = blockIdx.z;
    int cnt = g_counts[e];
    if (cnt > CAP) cnt = CAP;
    const int m0 = blockIdx.y * BM;
    if (m0 >= cnt) return;
    const int n0 = blockIdx.x * BN;

    __shared__ float As[BK][BM + 4];
    __shared__ float Bs[BK][BN];

    const int tid = threadIdx.x;
    const int tx  = tid & 15;
    const int ty  = tid >> 4;

    const int rowA = tid >> 2;
    const int cA   = (tid & 3) * 4;

    const float* arow0 = nullptr;
    const float* arow1 = nullptr;
    {
        int r0 = m0 + rowA;
        if (r0 < cnt) arow0 = g_h + (size_t)(e * CAP + r0) * DH;
        int r1 = m0 + rowA + 64;
        if (r1 < cnt) arow1 = g_h + (size_t)(e * CAP + r1) * DH;
    }

    const int kB = tid >> 4;
    const int nB = (tid & 15) * 4;
    const float* pB = w2 + (size_t)e * DH * DM + (size_t)kB * DM + n0 + nB;

    float acc[8][4];
#pragma unroll
    for (int i = 0; i < 8; i++)
#pragma unroll
        for (int j = 0; j < 4; j++) acc[i][j] = 0.f;

    for (int k0 = 0; k0 < DH; k0 += BK) {
        float4 a0 = arow0 ? *(const float4*)(arow0 + k0 + cA) : make_float4(0.f, 0.f, 0.f, 0.f);
        float4 a1 = arow1 ? *(const float4*)(arow1 + k0 + cA) : make_float4(0.f, 0.f, 0.f, 0.f);
        float4 b  = *(const float4*)(pB + (size_t)k0 * DM);

        As[cA + 0][rowA] = a0.x;  As[cA + 1][rowA] = a0.y;
        As[cA + 2][rowA] = a0.z;  As[cA + 3][rowA] = a0.w;
        As[cA + 0][rowA + 64] = a1.x;  As[cA + 1][rowA + 64] = a1.y;
        As[cA + 2][rowA + 64] = a1.z;  As[cA + 3][rowA + 64] = a1.w;
        *(float4*)&Bs[kB][nB] = b;
        __syncthreads();

#pragma unroll
        for (int k = 0; k < BK; k++) {
            float a[8], bv[4];
#pragma unroll
            for (int i = 0; i < 8; i++) a[i] = As[k][ty * 8 + i];
#pragma unroll
            for (int j = 0; j < 4; j++) bv[j] = Bs[k][tx * 4 + j];
#pragma unroll
            for (int i = 0; i < 8; i++)
#pragma unroll
                for (int j = 0; j < 4; j++)
                    acc[i][j] = fmaf(a[i], bv[j], acc[i][j]);
        }
        __syncthreads();
    }

#pragma unroll
    for (int i = 0; i < 8; i++) {
        int r = m0 + ty * 8 + i;
        if (r >= cnt) continue;
        float* yp = g_y + (size_t)(e * CAP + r) * DM + n0 + tx * 4;
#pragma unroll
        for (int j = 0; j < 4; j++) yp[j] = acc[i][j];
    }
}

// ---------------- combine: out[n] = sum_k ew[n,k] * y[slot(n,k)] ----------------
__global__ void combine_kernel(const float* __restrict__ ew, float* __restrict__ out) {
    int i = blockIdx.x * blockDim.x + threadIdx.x;     // float4 index
    int n = i / (DM / 4);
    int c = (i % (DM / 4)) * 4;

    float4 r = make_float4(0.f, 0.f, 0.f, 0.f);
#pragma unroll
    for (int k = 0; k < TOPK; k++) {
        int slot = g_slot_of_assign[n * TOPK + k];
        if (slot >= 0) {
            float w = ew[n * TOPK + k];
            float4 v = *(const float4*)(g_y + (size_t)slot * DM + c);
            r.x = fmaf(w, v.x, r.x);
            r.y = fmaf(w, v.y, r.y);
            r.z = fmaf(w, v.z, r.z);
            r.w = fmaf(w, v.w, r.w);
        }
    }
    *(float4*)(out + (size_t)n * DM + c) = r;
}

__global__ void counts_kernel(float* __restrict__ out_tail) {
    if (threadIdx.x < NEXP) out_tail[threadIdx.x] = (float)g_counts[threadIdx.x];
}

// ---------------- launch ----------------
extern "C" void kernel_launch(void* const* d_in, const int* in_sizes, int n_in,
                              void* d_out, int out_size) {
    const float* x  = (const float*)d_in[0];
    const float* ew = (const float*)d_in[1];
    const int*   ix = (const int*)  d_in[2];
    const float* w1 = (const float*)d_in[3];
    const float* w2 = (const float*)d_in[4];
    const float* w3 = (const float*)d_in[5];
    float* out = (float*)d_out;

    route_kernel<<<1, 256>>>(ix);

    dim3 g1(DH / BN, CAP / BM, NEXP);   // 32 x 20 x 8
    gemm1_kernel<<<g1, 256>>>(x, w1, w3);

    dim3 g2(DM / BN, CAP / BM, NEXP);
    gemm2_kernel<<<g2, 256>>>(w2);

    combine_kernel<<<(NTOK * (DM / 4)) / 256, 256>>>(ew, out);

    if (out_size >= NTOK * DM + NEXP)
        counts_kernel<<<1, 32>>>(out + (size_t)NTOK * DM);
}

// round 3
// speedup vs baseline: 1.4487x; 1.4487x over previous
#include <cuda_runtime.h>
#include <cuda_bf16.h>
#include <cstdint>

#define NTOK     8192
#define DM       2048
#define DH       2048
#define NEXP     8
#define TOPK     2
#define TASSIGN  (NTOK * TOPK)
#define CAP      2560

#define BM 128
#define BK 32
#define KIT (2048 / BK)      // 64 k-slabs
#define NSTAGE 4
#define STAGE_BYTES 32768    // A 16KB + B 16KB

// ---------------- scratch (device globals) ----------------
__device__ int   g_counts[NEXP];
__device__ int   g_tok[NEXP * CAP];
__device__ int   g_slot[TASSIGN];
__device__ __nv_bfloat16 g_xhi[(size_t)NTOK * DM];
__device__ __nv_bfloat16 g_xlo[(size_t)NTOK * DM];
__device__ __nv_bfloat16 g_w1h[(size_t)NEXP * DM * DH];
__device__ __nv_bfloat16 g_w1l[(size_t)NEXP * DM * DH];
__device__ __nv_bfloat16 g_w2h[(size_t)NEXP * DH * DM];
__device__ __nv_bfloat16 g_w2l[(size_t)NEXP * DH * DM];
__device__ __nv_bfloat16 g_w3h[(size_t)NEXP * DM * DH];
__device__ __nv_bfloat16 g_w3l[(size_t)NEXP * DM * DH];
__device__ __nv_bfloat16 g_hh[(size_t)NEXP * CAP * DH];
__device__ __nv_bfloat16 g_hl[(size_t)NEXP * CAP * DH];
__device__ float         g_y [(size_t)NEXP * CAP * DM];

// ---------------- helpers ----------------
__device__ __forceinline__ uint32_t smem_u32(const void* p) {
    uint32_t a;
    asm("{ .reg .u64 t; cvta.to.shared.u64 t, %1; cvt.u32.u64 %0, t; }" : "=r"(a) : "l"(p));
    return a;
}
__device__ __forceinline__ uint32_t swz(uint32_t o) { return o ^ ((o >> 3) & 0x70); }

__device__ __forceinline__ void cpasync16(uint32_t dst, const void* src) {
    asm volatile("cp.async.cg.shared.global [%0], [%1], 16;" :: "r"(dst), "l"(src) : "memory");
}
__device__ __forceinline__ void cp_commit() {
    asm volatile("cp.async.commit_group;" ::: "memory");
}
__device__ __forceinline__ void cp_wait2() {
    asm volatile("cp.async.wait_group 2;" ::: "memory");
}

__device__ __forceinline__ void ldsm4(uint32_t& r0, uint32_t& r1, uint32_t& r2, uint32_t& r3,
                                      uint32_t addr) {
    asm volatile("ldmatrix.sync.aligned.m8n8.x4.shared.b16 {%0,%1,%2,%3}, [%4];"
                 : "=r"(r0), "=r"(r1), "=r"(r2), "=r"(r3) : "r"(addr));
}

__device__ __forceinline__ void mma16816(float* d, const uint32_t* a, const uint32_t* b) {
    asm volatile(
        "mma.sync.aligned.m16n8k16.row.col.f32.bf16.bf16.f32 "
        "{%0,%1,%2,%3}, {%4,%5,%6,%7}, {%8,%9}, {%0,%1,%2,%3};"
        : "+f"(d[0]), "+f"(d[1]), "+f"(d[2]), "+f"(d[3])
        : "r"(a[0]), "r"(a[1]), "r"(a[2]), "r"(a[3]), "r"(b[0]), "r"(b[1]));
}

// ---------------- routing ----------------
__global__ void route_kernel(const int* __restrict__ idx) {
    int w    = threadIdx.x >> 5;
    int lane = threadIdx.x & 31;
    if (w >= NEXP) return;
    int base = 0;
    for (int t0 = 0; t0 < TASSIGN; t0 += 32) {
        int t = t0 + lane;
        int e = idx[t];
        bool m = (e == w);
        unsigned mask = __ballot_sync(0xffffffffu, m);
        if (m) {
            int rank = base + __popc(mask & ((1u << lane) - 1u));
            int slot = -1;
            if (rank < CAP) {
                slot = w * CAP + rank;
                g_tok[slot] = t / TOPK;
            }
            g_slot[t] = slot;
        }
        base += __popc(mask);
    }
    if (lane == 0) g_counts[w] = base;
}

// ---------------- x split ----------------
__global__ void xsplit_kernel(const float* __restrict__ x) {
    size_t i = (size_t)blockIdx.x * blockDim.x + threadIdx.x;
    float v = x[i];
    __nv_bfloat16 hi = __float2bfloat16(v);
    __nv_bfloat16 lo = __float2bfloat16(v - __bfloat162float(hi));
    g_xhi[i] = hi;
    g_xlo[i] = lo;
}

// ---------------- weight transpose + split ----------------
template <int T>
__global__ void wprep_kernel(const float* __restrict__ w) {
    __shared__ float t[32][33];
    int e  = blockIdx.z;
    int d0 = blockIdx.y * 32, h0 = blockIdx.x * 32;
    int tx = threadIdx.x, ty = threadIdx.y;
    const float* src = w + (size_t)e * DM * DH;
#pragma unroll
    for (int i = 0; i < 32; i += 8)
        t[ty + i][tx] = src[(size_t)(d0 + ty + i) * DH + h0 + tx];
    __syncthreads();
    __nv_bfloat16* dh = (T == 1) ? g_w1h : (T == 2) ? g_w2h : g_w3h;
    __nv_bfloat16* dl = (T == 1) ? g_w1l : (T == 2) ? g_w2l : g_w3l;
#pragma unroll
    for (int i = 0; i < 32; i += 8) {
        float v = t[tx][ty + i];
        __nv_bfloat16 hi = __float2bfloat16(v);
        __nv_bfloat16 lo = __float2bfloat16(v - __bfloat162float(hi));
        size_t o = (size_t)e * DM * DH + (size_t)(h0 + ty + i) * DM + d0 + tx;
        dh[o] = hi;
        dl[o] = lo;
    }
}

// ---------------- HMMA GEMM ----------------
// MODE 1: fused x@w1 / x@w3 + SwiGLU -> g_hh/g_hl (CTA: 128 M x 64 N of each matrix)
// MODE 2: h@w2 -> g_y               (CTA: 128 M x 128 N)
template <int MODE>
__global__ __launch_bounds__(256, 1) void hmma_gemm_kernel() {
    const int e = blockIdx.z;
    int cnt = g_counts[e];
    if (cnt > CAP) cnt = CAP;
    const int m0 = blockIdx.y * BM;
    if (m0 >= cnt) return;
    const int n0 = blockIdx.x * ((MODE == 1) ? 64 : 128);

    extern __shared__ __align__(1024) char smem[];
    uint32_t sb = smem_u32(smem);

    const int tid  = threadIdx.x;
    const int lane = tid & 31;
    const int wid  = tid >> 5;

    // ---- per-thread cp.async source/dest setup ----
    const int r    = tid >> 1;       // smem row 0..127
    const int half = tid & 1;        // 0: hi, 1: lo
    const __nv_bfloat16* pa;
    const __nv_bfloat16* pb;
    if (MODE == 1) {
        int tok = g_tok[e * CAP + m0 + r];
        pa = (half ? g_xlo : g_xhi) + (size_t)tok * DM;
        int bn = n0 + (r & 63);
        const __nv_bfloat16* w = (r < 64) ? (half ? g_w1l : g_w1h)
                                          : (half ? g_w3l : g_w3h);
        pb = w + ((size_t)e * DH + bn) * DM;
    } else {
        pa = (half ? g_hl : g_hh) + ((size_t)e * CAP + m0 + r) * DH;
        pb = (half ? g_w2l : g_w2h) + ((size_t)e * DH + n0 + r) * DM;
    }
    uint32_t soA[4], soB[4];
#pragma unroll
    for (int j = 0; j < 4; j++) {
        uint32_t off = swz((uint32_t)(r * 128 + half * 64 + j * 16));
        soA[j] = sb + off;
        soB[j] = sb + 16384 + off;
    }

    // ---- warp tiling ----
    int wm, wn, mat;
    if (MODE == 1) { wm = wid & 1; wn = (wid >> 1) & 1; mat = wid >> 2; }
    else           { wm = wid & 1; wn = wid >> 1;       mat = 0; }
    const int mbase = wm * 64;
    const int nbase = (MODE == 1) ? (mat * 64 + wn * 32) : (wn * 32);

    const int lrow = lane & 15;
    const int lkb  = (lane & 16) ? 16 : 0;

    float acc[4][4][4];
#pragma unroll
    for (int mi = 0; mi < 4; mi++)
#pragma unroll
        for (int ni = 0; ni < 4; ni++)
#pragma unroll
            for (int q = 0; q < 4; q++) acc[mi][ni][q] = 0.f;

    // ---- prologue ----
#pragma unroll
    for (int s = 0; s < NSTAGE - 1; s++) {
        int k0 = s * BK;
        uint32_t o = s * STAGE_BYTES;
#pragma unroll
        for (int j = 0; j < 4; j++) cpasync16(soA[j] + o, pa + k0 + j * 8);
#pragma unroll
        for (int j = 0; j < 4; j++) cpasync16(soB[j] + o, pb + k0 + j * 8);
        cp_commit();
    }

    const int bco[4] = {0, 32, 64, 96};   // chunk byte offsets: hi0, hi1, lo0, lo1

    for (int kt = 0; kt < KIT; kt++) {
        cp_wait2();
        __syncthreads();

        // issue slab kt+3
        {
            int ks = kt + NSTAGE - 1;
            if (ks < KIT) {
                int k0 = ks * BK;
                uint32_t o = (ks & (NSTAGE - 1)) * STAGE_BYTES;
#pragma unroll
                for (int j = 0; j < 4; j++) cpasync16(soA[j] + o, pa + k0 + j * 8);
#pragma unroll
                for (int j = 0; j < 4; j++) cpasync16(soB[j] + o, pb + k0 + j * 8);
            }
            cp_commit();
        }

        // compute slab kt
        uint32_t aB = sb + (kt & (NSTAGE - 1)) * STAGE_BYTES;
        uint32_t bB = aB + 16384;

        uint32_t bf[4][4][2];
#pragma unroll
        for (int c = 0; c < 4; c++) {
#pragma unroll
            for (int g = 0; g < 2; g++) {
                uint32_t q0, q1, q2, q3;
                uint32_t addr = bB + swz((uint32_t)((nbase + g * 16 + lrow) * 128 + bco[c] + lkb));
                ldsm4(q0, q1, q2, q3, addr);
                bf[c][g * 2 + 0][0] = q0; bf[c][g * 2 + 0][1] = q2;
                bf[c][g * 2 + 1][0] = q1; bf[c][g * 2 + 1][1] = q3;
            }
        }

        // term schedule: Achunk -> list of Bchunks
        // A0(hi0)->B0(hi0),B2(lo0); A1(hi1)->B1,B3; A2(lo0)->B0; A3(lo1)->B1
#pragma unroll
        for (int ac = 0; ac < 4; ac++) {
            uint32_t af[4][4];
#pragma unroll
            for (int mi = 0; mi < 4; mi++) {
                uint32_t addr = aB + swz((uint32_t)((mbase + mi * 16 + lrow) * 128 + bco[ac] + lkb));
                ldsm4(af[mi][0], af[mi][1], af[mi][2], af[mi][3], addr);
            }
            const int bc0 = (ac < 2) ? ac : (ac - 2);
#pragma unroll
            for (int mi = 0; mi < 4; mi++)
#pragma unroll
                for (int ni = 0; ni < 4; ni++)
                    mma16816(acc[mi][ni], af[mi], bf[bc0][ni]);
            if (ac < 2) {
                const int bc1 = ac + 2;
#pragma unroll
                for (int mi = 0; mi < 4; mi++)
#pragma unroll
                    for (int ni = 0; ni < 4; ni++)
                        mma16816(acc[mi][ni], af[mi], bf[bc1][ni]);
            }
        }
    }

    // ---- epilogue ----
    __syncthreads();
    if (MODE == 1) {
        float* fb = (float*)smem;   // 128 x 64 fp32 = 32KB (reuse stage 0)
        if (mat == 1) {
#pragma unroll
            for (int mi = 0; mi < 4; mi++)
#pragma unroll
                for (int ni = 0; ni < 4; ni++) {
                    int ml = mbase + mi * 16 + (lane >> 2);
                    int nl = wn * 32 + ni * 8 + 2 * (lane & 3);
                    fb[ml * 64 + nl]           = acc[mi][ni][0];
                    fb[ml * 64 + nl + 1]       = acc[mi][ni][1];
                    fb[(ml + 8) * 64 + nl]     = acc[mi][ni][2];
                    fb[(ml + 8) * 64 + nl + 1] = acc[mi][ni][3];
                }
        }
        __syncthreads();
        if (mat == 0) {
#pragma unroll
            for (int mi = 0; mi < 4; mi++)
#pragma unroll
                for (int ni = 0; ni < 4; ni++) {
                    int ml = mbase + mi * 16 + (lane >> 2);
                    int nl = wn * 32 + ni * 8 + 2 * (lane & 3);
#pragma unroll
                    for (int hrow = 0; hrow < 2; hrow++) {
                        int mloc = ml + hrow * 8;
                        int row  = m0 + mloc;
                        if (row >= cnt) continue;
                        float a10 = acc[mi][ni][2 * hrow + 0];
                        float a11 = acc[mi][ni][2 * hrow + 1];
                        float a30 = fb[mloc * 64 + nl];
                        float a31 = fb[mloc * 64 + nl + 1];
                        float h0 = (a10 / (1.f + __expf(-a10))) * a30;
                        float h1 = (a11 / (1.f + __expf(-a11))) * a31;
                        __nv_bfloat16 h0h = __float2bfloat16(h0);
                        __nv_bfloat16 h1h = __float2bfloat16(h1);
                        __nv_bfloat16 h0l = __float2bfloat16(h0 - __bfloat162float(h0h));
                        __nv_bfloat16 h1l = __float2bfloat16(h1 - __bfloat162float(h1h));
                        uint32_t ph = (uint32_t)__bfloat16_as_ushort(h0h) |
                                      ((uint32_t)__bfloat16_as_ushort(h1h) << 16);
                        uint32_t pl = (uint32_t)__bfloat16_as_ushort(h0l) |
                                      ((uint32_t)__bfloat16_as_ushort(h1l) << 16);
                        size_t o = ((size_t)e * CAP + row) * DH + n0 + nl;
                        *(uint32_t*)(g_hh + o) = ph;
                        *(uint32_t*)(g_hl + o) = pl;
                    }
                }
        }
    } else {
#pragma unroll
        for (int mi = 0; mi < 4; mi++)
#pragma unroll
            for (int ni = 0; ni < 4; ni++) {
                int ml = mbase + mi * 16 + (lane >> 2);
                int nl = nbase + ni * 8 + 2 * (lane & 3);
#pragma unroll
                for (int hrow = 0; hrow < 2; hrow++) {
                    int row = m0 + ml + hrow * 8;
                    if (row >= cnt) continue;
                    float2 v = make_float2(acc[mi][ni][2 * hrow], acc[mi][ni][2 * hrow + 1]);
                    *(float2*)(g_y + ((size_t)e * CAP + row) * DM + n0 + nl) = v;
                }
            }
    }
}

// ---------------- combine ----------------
__global__ void combine_kernel(const float* __restrict__ ew, float* __restrict__ out) {
    int i = blockIdx.x * blockDim.x + threadIdx.x;
    int n = i / (DM / 4);
    int c = (i % (DM / 4)) * 4;
    float4 r = make_float4(0.f, 0.f, 0.f, 0.f);
#pragma unroll
    for (int k = 0; k < TOPK; k++) {
        int slot = g_slot[n * TOPK + k];
        if (slot >= 0) {
            float w = ew[n * TOPK + k];
            float4 v = *(const float4*)(g_y + (size_t)slot * DM + c);
            r.x = fmaf(w, v.x, r.x);
            r.y = fmaf(w, v.y, r.y);
            r.z = fmaf(w, v.z, r.z);
            r.w = fmaf(w, v.w, r.w);
        }
    }
    *(float4*)(out + (size_t)n * DM + c) = r;
}

__global__ void counts_kernel(float* __restrict__ out_tail) {
    if (threadIdx.x < NEXP) out_tail[threadIdx.x] = (float)g_counts[threadIdx.x];
}

// ---------------- launch ----------------
extern "C" void kernel_launch(void* const* d_in, const int* in_sizes, int n_in,
                              void* d_out, int out_size) {
    const float* x  = (const float*)d_in[0];
    const float* ew = (const float*)d_in[1];
    const int*   ix = (const int*)  d_in[2];
    const float* w1 = (const float*)d_in[3];
    const float* w2 = (const float*)d_in[4];
    const float* w3 = (const float*)d_in[5];
    float* out = (float*)d_out;

    const int SMEM = NSTAGE * STAGE_BYTES;   // 131072
    cudaFuncSetAttribute(hmma_gemm_kernel<1>, cudaFuncAttributeMaxDynamicSharedMemorySize, SMEM);
    cudaFuncSetAttribute(hmma_gemm_kernel<2>, cudaFuncAttributeMaxDynamicSharedMemorySize, SMEM);

    route_kernel<<<1, 256>>>(ix);
    xsplit_kernel<<<(NTOK * DM) / 256, 256>>>(x);

    dim3 wg(DM / 32, DH / 32, NEXP);
    dim3 wb(32, 8);
    wprep_kernel<1><<<wg, wb>>>(w1);
    wprep_kernel<2><<<wg, wb>>>(w2);
    wprep_kernel<3><<<wg, wb>>>(w3);

    dim3 g1(DH / 64, CAP / BM, NEXP);    // 32 x 20 x 8
    hmma_gemm_kernel<1><<<g1, 256, SMEM>>>();

    dim3 g2(DM / 128, CAP / BM, NEXP);   // 16 x 20 x 8
    hmma_gemm_kernel<2><<<g2, 256, SMEM>>>();

    combine_kernel<<<(NTOK * (DM / 4)) / 256, 256>>>(ew, out);

    if (out_size >= NTOK * DM + NEXP)
        counts_kernel<<<1, 32>>>(out + (size_t)NTOK * DM);
}

// round 4
// speedup vs baseline: 2.1296x; 1.4700x over previous
#include <cuda_runtime.h>
#include <cuda_fp16.h>
#include <cstdint>

#define NTOK     8192
#define DM       2048
#define DH       2048
#define NEXP     8
#define TOPK     2
#define TASSIGN  (NTOK * TOPK)
#define CAP      2560

#define BM 128
#define BK 32
#define KIT (2048 / BK)        // 64 k-slabs
#define NSTAGE 4
#define STAGE_BYTES 24576      // A 16KB + B 8KB

// ---------------- scratch (device globals) ----------------
__device__ int    g_counts[NEXP];
__device__ int    g_tok[NEXP * CAP];
__device__ int    g_slot[TASSIGN];
__device__ __half g_xhi[(size_t)NTOK * DM];
__device__ __half g_xlo[(size_t)NTOK * DM];
__device__ __half g_w1t[(size_t)NEXP * DM * DH];
__device__ __half g_w2t[(size_t)NEXP * DH * DM];
__device__ __half g_w3t[(size_t)NEXP * DM * DH];
__device__ __half g_hh[(size_t)NEXP * CAP * DH];
__device__ __half g_hl[(size_t)NEXP * CAP * DH];
__device__ float  g_y [(size_t)NEXP * CAP * DM];

// ---------------- helpers ----------------
__device__ __forceinline__ uint32_t smem_u32(const void* p) {
    uint32_t a;
    asm("{ .reg .u64 t; cvta.to.shared.u64 t, %1; cvt.u32.u64 %0, t; }" : "=r"(a) : "l"(p));
    return a;
}
__device__ __forceinline__ uint32_t swz128(uint32_t o) { return o ^ ((o >> 3) & 0x70); }
__device__ __forceinline__ uint32_t swz64(uint32_t o)  { return o ^ ((o >> 3) & 0x30); }

__device__ __forceinline__ void cpasync16(uint32_t dst, const void* src) {
    asm volatile("cp.async.cg.shared.global [%0], [%1], 16;" :: "r"(dst), "l"(src) : "memory");
}
__device__ __forceinline__ void cp_commit() {
    asm volatile("cp.async.commit_group;" ::: "memory");
}
__device__ __forceinline__ void cp_wait2() {
    asm volatile("cp.async.wait_group 2;" ::: "memory");
}

__device__ __forceinline__ void ldsm4(uint32_t& r0, uint32_t& r1, uint32_t& r2, uint32_t& r3,
                                      uint32_t addr) {
    asm volatile("ldmatrix.sync.aligned.m8n8.x4.shared.b16 {%0,%1,%2,%3}, [%4];"
                 : "=r"(r0), "=r"(r1), "=r"(r2), "=r"(r3) : "r"(addr));
}

__device__ __forceinline__ void mma16816(float* d, const uint32_t* a, const uint32_t* b) {
    asm volatile(
        "mma.sync.aligned.m16n8k16.row.col.f32.f16.f16.f32 "
        "{%0,%1,%2,%3}, {%4,%5,%6,%7}, {%8,%9}, {%0,%1,%2,%3};"
        : "+f"(d[0]), "+f"(d[1]), "+f"(d[2]), "+f"(d[3])
        : "r"(a[0]), "r"(a[1]), "r"(a[2]), "r"(a[3]), "r"(b[0]), "r"(b[1]));
}

// ---------------- routing ----------------
__global__ void route_kernel(const int* __restrict__ idx) {
    int w    = threadIdx.x >> 5;
    int lane = threadIdx.x & 31;
    if (w >= NEXP) return;
    int base = 0;
    for (int t0 = 0; t0 < TASSIGN; t0 += 32) {
        int t = t0 + lane;
        int e = idx[t];
        bool m = (e == w);
        unsigned mask = __ballot_sync(0xffffffffu, m);
        if (m) {
            int rank = base + __popc(mask & ((1u << lane) - 1u));
            int slot = -1;
            if (rank < CAP) {
                slot = w * CAP + rank;
                g_tok[slot] = t / TOPK;
            }
            g_slot[t] = slot;
        }
        base += __popc(mask);
    }
    if (lane == 0) g_counts[w] = base;
}

// ---------------- x split: f32 -> fp16 hi/lo ----------------
__global__ void xsplit_kernel(const float* __restrict__ x) {
    size_t i = (size_t)blockIdx.x * blockDim.x + threadIdx.x;
    float v = x[i];
    __half hi = __float2half_rn(v);
    __half lo = __float2half_rn(v - __half2float(hi));
    g_xhi[i] = hi;
    g_xlo[i] = lo;
}

// ---------------- weight transpose + fp16 convert (all 3 weights) ----------------
__global__ void wprep_kernel(const float* __restrict__ w1,
                             const float* __restrict__ w2,
                             const float* __restrict__ w3) {
    __shared__ float t[32][33];
    int z  = blockIdx.z;
    int e  = z & 7;
    int T  = z >> 3;                       // 0: w1, 1: w2, 2: w3
    const float* w = (T == 0) ? w1 : (T == 1) ? w2 : w3;
    __half* dst    = (T == 0) ? g_w1t : (T == 1) ? g_w2t : g_w3t;
    int d0 = blockIdx.y * 32, h0 = blockIdx.x * 32;
    int tx = threadIdx.x, ty = threadIdx.y;
    const float* src = w + (size_t)e * DM * DH;
#pragma unroll
    for (int i = 0; i < 32; i += 8)
        t[ty + i][tx] = src[(size_t)(d0 + ty + i) * DH + h0 + tx];
    __syncthreads();
#pragma unroll
    for (int i = 0; i < 32; i += 8) {
        float v = t[tx][ty + i];
        size_t o = (size_t)e * DM * DH + (size_t)(h0 + ty + i) * DM + d0 + tx;
        dst[o] = __float2half_rn(v);
    }
}

// ---------------- HMMA GEMM (fp16 2-term split) ----------------
// MODE 1: fused x@w1 / x@w3 + SwiGLU -> g_hh/g_hl (CTA: 128 M x 64 N of each)
// MODE 2: h@w2 -> g_y                (CTA: 128 M x 128 N)
template <int MODE>
__global__ __launch_bounds__(256, 1) void hmma_gemm_kernel() {
    const int e = blockIdx.z;
    int cnt = g_counts[e];
    if (cnt > CAP) cnt = CAP;
    const int m0 = blockIdx.y * BM;
    if (m0 >= cnt) return;
    const int n0 = blockIdx.x * ((MODE == 1) ? 64 : 128);

    extern __shared__ __align__(1024) char smem[];
    uint32_t sb = smem_u32(smem);

    const int tid  = threadIdx.x;
    const int lane = tid & 31;
    const int wid  = tid >> 5;

    // ---- A cp.async mapping: thread t -> row r = t>>1, half = t&1 (hi/lo); 4x16B
    const int r    = tid >> 1;
    const int half = tid & 1;
    const __half* pa;
    if (MODE == 1) {
        int tok = g_tok[e * CAP + m0 + r];
        pa = (half ? g_xlo : g_xhi) + (size_t)tok * DM;
    } else {
        pa = (half ? g_hl : g_hh) + ((size_t)e * CAP + m0 + r) * DH;
    }
    uint32_t soA[4];
#pragma unroll
    for (int j = 0; j < 4; j++)
        soA[j] = sb + swz128((uint32_t)(r * 128 + half * 64 + j * 16));

    // ---- B cp.async mapping: thread t -> row rb = t>>1, 32B chunk cb = t&1; 2x16B
    const int rb = tid >> 1;
    const int cb = tid & 1;
    const __half* pb;
    if (MODE == 1) {
        if (rb < 64) pb = g_w1t + ((size_t)e * DH + n0 + rb) * DM;
        else         pb = g_w3t + ((size_t)e * DH + n0 + rb - 64) * DM;
    } else {
        pb = g_w2t + ((size_t)e * DM + n0 + rb) * DH;
    }
    pb += cb * 16;
    uint32_t soB[2];
#pragma unroll
    for (int j = 0; j < 2; j++)
        soB[j] = sb + 16384 + swz64((uint32_t)(rb * 64 + cb * 32 + j * 16));

    // ---- warp tiling ----
    int wm, wn, mat;
    if (MODE == 1) { wm = wid & 1; wn = (wid >> 1) & 1; mat = wid >> 2; }
    else           { wm = wid & 1; wn = wid >> 1;       mat = 0; }
    const int mbase = wm * 64;
    const int nbB   = (MODE == 1) ? (mat * 64 + wn * 32) : (wn * 32);

    const int lrow = lane & 15;
    const int lkb  = (lane & 16) ? 16 : 0;

    float acc[4][4][4];
#pragma unroll
    for (int mi = 0; mi < 4; mi++)
#pragma unroll
        for (int ni = 0; ni < 4; ni++)
#pragma unroll
            for (int q = 0; q < 4; q++) acc[mi][ni][q] = 0.f;

    // ---- prologue ----
#pragma unroll
    for (int s = 0; s < NSTAGE - 1; s++) {
        int k0 = s * BK;
        uint32_t o = s * STAGE_BYTES;
#pragma unroll
        for (int j = 0; j < 4; j++) cpasync16(soA[j] + o, pa + k0 + j * 8);
#pragma unroll
        for (int j = 0; j < 2; j++) cpasync16(soB[j] + o, pb + k0 + j * 8);
        cp_commit();
    }

    const int bco[4] = {0, 32, 64, 96};   // A chunks: hi-k0, hi-k1, lo-k0, lo-k1

    for (int kt = 0; kt < KIT; kt++) {
        cp_wait2();
        __syncthreads();

        {   // issue slab kt+3
            int ks = kt + NSTAGE - 1;
            if (ks < KIT) {
                int k0 = ks * BK;
                uint32_t o = (ks & (NSTAGE - 1)) * STAGE_BYTES;
#pragma unroll
                for (int j = 0; j < 4; j++) cpasync16(soA[j] + o, pa + k0 + j * 8);
#pragma unroll
                for (int j = 0; j < 2; j++) cpasync16(soB[j] + o, pb + k0 + j * 8);
            }
            cp_commit();
        }

        uint32_t aB = sb + (kt & (NSTAGE - 1)) * STAGE_BYTES;
        uint32_t bB = aB + 16384;

        // B fragments: 2 k-chunks x 4 n-tiles
        uint32_t bf[2][4][2];
#pragma unroll
        for (int c = 0; c < 2; c++) {
#pragma unroll
            for (int g = 0; g < 2; g++) {
                uint32_t q0, q1, q2, q3;
                uint32_t addr = bB + swz64((uint32_t)((nbB + g * 16 + lrow) * 64 + c * 32 + lkb));
                ldsm4(q0, q1, q2, q3, addr);
                bf[c][g * 2 + 0][0] = q0; bf[c][g * 2 + 0][1] = q2;
                bf[c][g * 2 + 1][0] = q1; bf[c][g * 2 + 1][1] = q3;
            }
        }

        // schedule: Ahi0->B0, Ahi1->B1, Alo0->B0, Alo1->B1  (64 MMAs)
#pragma unroll
        for (int ac = 0; ac < 4; ac++) {
            uint32_t af[4][4];
#pragma unroll
            for (int mi = 0; mi < 4; mi++) {
                uint32_t addr = aB + swz128((uint32_t)((mbase + mi * 16 + lrow) * 128 + bco[ac] + lkb));
                ldsm4(af[mi][0], af[mi][1], af[mi][2], af[mi][3], addr);
            }
            const int bc = ac & 1;
#pragma unroll
            for (int mi = 0; mi < 4; mi++)
#pragma unroll
                for (int ni = 0; ni < 4; ni++)
                    mma16816(acc[mi][ni], af[mi], bf[bc][ni]);
        }
    }

    // ---- epilogue ----
    __syncthreads();
    if (MODE == 1) {
        float* fb = (float*)smem;   // 128 x 64 fp32 = 32KB scratch (reuse stages)
        if (mat == 1) {
#pragma unroll
            for (int mi = 0; mi < 4; mi++)
#pragma unroll
                for (int ni = 0; ni < 4; ni++) {
                    int ml = mbase + mi * 16 + (lane >> 2);
                    int nl = wn * 32 + ni * 8 + 2 * (lane & 3);
                    fb[ml * 64 + nl]           = acc[mi][ni][0];
                    fb[ml * 64 + nl + 1]       = acc[mi][ni][1];
                    fb[(ml + 8) * 64 + nl]     = acc[mi][ni][2];
                    fb[(ml + 8) * 64 + nl + 1] = acc[mi][ni][3];
                }
        }
        __syncthreads();
        if (mat == 0) {
#pragma unroll
            for (int mi = 0; mi < 4; mi++)
#pragma unroll
                for (int ni = 0; ni < 4; ni++) {
                    int ml = mbase + mi * 16 + (lane >> 2);
                    int nl = wn * 32 + ni * 8 + 2 * (lane & 3);
#pragma unroll
                    for (int hrow = 0; hrow < 2; hrow++) {
                        int mloc = ml + hrow * 8;
                        int row  = m0 + mloc;
                        if (row >= cnt) continue;
                        float a10 = acc[mi][ni][2 * hrow + 0];
                        float a11 = acc[mi][ni][2 * hrow + 1];
                        float a30 = fb[mloc * 64 + nl];
                        float a31 = fb[mloc * 64 + nl + 1];
                        float h0 = (a10 / (1.f + __expf(-a10))) * a30;
                        float h1 = (a11 / (1.f + __expf(-a11))) * a31;
                        __half h0h = __float2half_rn(h0);
                        __half h1h = __float2half_rn(h1);
                        __half h0l = __float2half_rn(h0 - __half2float(h0h));
                        __half h1l = __float2half_rn(h1 - __half2float(h1h));
                        uint32_t ph = (uint32_t)__half_as_ushort(h0h) |
                                      ((uint32_t)__half_as_ushort(h1h) << 16);
                        uint32_t pl = (uint32_t)__half_as_ushort(h0l) |
                                      ((uint32_t)__half_as_ushort(h1l) << 16);
                        size_t o = ((size_t)e * CAP + row) * DH + n0 + nl;
                        *(uint32_t*)(g_hh + o) = ph;
                        *(uint32_t*)(g_hl + o) = pl;
                    }
                }
        }
    } else {
#pragma unroll
        for (int mi = 0; mi < 4; mi++)
#pragma unroll
            for (int ni = 0; ni < 4; ni++) {
                int ml = mbase + mi * 16 + (lane >> 2);
                int nl = nbB + ni * 8 + 2 * (lane & 3);
#pragma unroll
                for (int hrow = 0; hrow < 2; hrow++) {
                    int row = m0 + ml + hrow * 8;
                    if (row >= cnt) continue;
                    float2 v = make_float2(acc[mi][ni][2 * hrow], acc[mi][ni][2 * hrow + 1]);
                    *(float2*)(g_y + ((size_t)e * CAP + row) * DM + n0 + nl) = v;
                }
            }
    }
}

// ---------------- combine ----------------
__global__ void combine_kernel(const float* __restrict__ ew, float* __restrict__ out) {
    int i = blockIdx.x * blockDim.x + threadIdx.x;
    int n = i / (DM / 4);
    int c = (i % (DM / 4)) * 4;
    float4 r = make_float4(0.f, 0.f, 0.f, 0.f);
#pragma unroll
    for (int k = 0; k < TOPK; k++) {
        int slot = g_slot[n * TOPK + k];
        if (slot >= 0) {
            float w = ew[n * TOPK + k];
            float4 v = *(const float4*)(g_y + (size_t)slot * DM + c);
            r.x = fmaf(w, v.x, r.x);
            r.y = fmaf(w, v.y, r.y);
            r.z = fmaf(w, v.z, r.z);
            r.w = fmaf(w, v.w, r.w);
        }
    }
    *(float4*)(out + (size_t)n * DM + c) = r;
}

__global__ void counts_kernel(float* __restrict__ out_tail) {
    if (threadIdx.x < NEXP) out_tail[threadIdx.x] = (float)g_counts[threadIdx.x];
}

// ---------------- launch ----------------
extern "C" void kernel_launch(void* const* d_in, const int* in_sizes, int n_in,
                              void* d_out, int out_size) {
    const float* x  = (const float*)d_in[0];
    const float* ew = (const float*)d_in[1];
    const int*   ix = (const int*)  d_in[2];
    const float* w1 = (const float*)d_in[3];
    const float* w2 = (const float*)d_in[4];
    const float* w3 = (const float*)d_in[5];
    float* out = (float*)d_out;

    const int SMEM = NSTAGE * STAGE_BYTES;   // 98304
    cudaFuncSetAttribute(hmma_gemm_kernel<1>, cudaFuncAttributeMaxDynamicSharedMemorySize, SMEM);
    cudaFuncSetAttribute(hmma_gemm_kernel<2>, cudaFuncAttributeMaxDynamicSharedMemorySize, SMEM);

    route_kernel<<<1, 256>>>(ix);
    xsplit_kernel<<<(NTOK * DM) / 256, 256>>>(x);

    dim3 wg(DH / 32, DM / 32, 3 * NEXP);
    dim3 wb(32, 8);
    wprep_kernel<<<wg, wb>>>(w1, w2, w3);

    dim3 g1(DH / 64, CAP / BM, NEXP);    // 32 x 20 x 8
    hmma_gemm_kernel<1><<<g1, 256, SMEM>>>();

    dim3 g2(DM / 128, CAP / BM, NEXP);   // 16 x 20 x 8
    hmma_gemm_kernel<2><<<g2, 256, SMEM>>>();

    combine_kernel<<<(NTOK * (DM / 4)) / 256, 256>>>(ew, out);

    if (out_size >= NTOK * DM + NEXP)
        counts_kernel<<<1, 32>>>(out + (size_t)NTOK * DM);
}

// round 5
// speedup vs baseline: 2.3096x; 1.0845x over previous
#include <cuda_runtime.h>
#include <cuda_fp16.h>
#include <cstdint>

#define NTOK     8192
#define DM       2048
#define DH       2048
#define NEXP     8
#define TOPK     2
#define TASSIGN  (NTOK * TOPK)
#define CAP      2560

#define BM 128
#define BK 32
#define KIT (2048 / BK)        // 64 k-slabs
#define NSTAGE 3
#define STAGE_BYTES 24576      // A 16KB + B 8KB

// ---------------- scratch (device globals) ----------------
__device__ int    g_counts[NEXP];
__device__ int    g_tok[NEXP * CAP];
__device__ int    g_slot[TASSIGN];
__device__ __half g_xhi[(size_t)NTOK * DM];
__device__ __half g_xlo[(size_t)NTOK * DM];
__device__ __half g_w1t[(size_t)NEXP * DM * DH];
__device__ __half g_w2t[(size_t)NEXP * DH * DM];
__device__ __half g_w3t[(size_t)NEXP * DM * DH];
__device__ __half g_hh[(size_t)NEXP * CAP * DH];
__device__ __half g_hl[(size_t)NEXP * CAP * DH];
__device__ float  g_y [(size_t)NEXP * CAP * DM];

// ---------------- helpers ----------------
__device__ __forceinline__ uint32_t smem_u32(const void* p) {
    uint32_t a;
    asm("{ .reg .u64 t; cvta.to.shared.u64 t, %1; cvt.u32.u64 %0, t; }" : "=r"(a) : "l"(p));
    return a;
}
__device__ __forceinline__ uint32_t swz128(uint32_t o) { return o ^ ((o >> 3) & 0x70); }
__device__ __forceinline__ uint32_t swz64(uint32_t o)  { return o ^ ((o >> 3) & 0x30); }

__device__ __forceinline__ void cpasync16(uint32_t dst, const void* src) {
    asm volatile("cp.async.cg.shared.global [%0], [%1], 16;" :: "r"(dst), "l"(src) : "memory");
}
__device__ __forceinline__ void cp_commit() {
    asm volatile("cp.async.commit_group;" ::: "memory");
}
__device__ __forceinline__ void cp_wait1() {
    asm volatile("cp.async.wait_group 1;" ::: "memory");
}

__device__ __forceinline__ void ldsm4(uint32_t& r0, uint32_t& r1, uint32_t& r2, uint32_t& r3,
                                      uint32_t addr) {
    asm volatile("ldmatrix.sync.aligned.m8n8.x4.shared.b16 {%0,%1,%2,%3}, [%4];"
                 : "=r"(r0), "=r"(r1), "=r"(r2), "=r"(r3) : "r"(addr));
}

__device__ __forceinline__ void mma16816(float* d, const uint32_t* a, const uint32_t* b) {
    asm volatile(
        "mma.sync.aligned.m16n8k16.row.col.f32.f16.f16.f32 "
        "{%0,%1,%2,%3}, {%4,%5,%6,%7}, {%8,%9}, {%0,%1,%2,%3};"
        : "+f"(d[0]), "+f"(d[1]), "+f"(d[2]), "+f"(d[3])
        : "r"(a[0]), "r"(a[1]), "r"(a[2]), "r"(a[3]), "r"(b[0]), "r"(b[1]));
}

// ---------------- routing ----------------
__global__ void route_kernel(const int* __restrict__ idx) {
    int w    = threadIdx.x >> 5;
    int lane = threadIdx.x & 31;
    if (w >= NEXP) return;
    int base = 0;
    for (int t0 = 0; t0 < TASSIGN; t0 += 32) {
        int t = t0 + lane;
        int e = idx[t];
        bool m = (e == w);
        unsigned mask = __ballot_sync(0xffffffffu, m);
        if (m) {
            int rank = base + __popc(mask & ((1u << lane) - 1u));
            int slot = -1;
            if (rank < CAP) {
                slot = w * CAP + rank;
                g_tok[slot] = t / TOPK;
            }
            g_slot[t] = slot;
        }
        base += __popc(mask);
    }
    if (lane == 0) g_counts[w] = base;
}

// ---------------- x split: f32 -> fp16 hi/lo ----------------
__global__ void xsplit_kernel(const float* __restrict__ x) {
    size_t i = (size_t)blockIdx.x * blockDim.x + threadIdx.x;
    float v = x[i];
    __half hi = __float2half_rn(v);
    __half lo = __float2half_rn(v - __half2float(hi));
    g_xhi[i] = hi;
    g_xlo[i] = lo;
}

// ---------------- weight transpose + fp16 convert (all 3 weights) ----------------
__global__ void wprep_kernel(const float* __restrict__ w1,
                             const float* __restrict__ w2,
                             const float* __restrict__ w3) {
    __shared__ float t[32][33];
    int z  = blockIdx.z;
    int e  = z & 7;
    int T  = z >> 3;                       // 0: w1, 1: w2, 2: w3
    const float* w = (T == 0) ? w1 : (T == 1) ? w2 : w3;
    __half* dst    = (T == 0) ? g_w1t : (T == 1) ? g_w2t : g_w3t;
    int d0 = blockIdx.y * 32, h0 = blockIdx.x * 32;
    int tx = threadIdx.x, ty = threadIdx.y;
    const float* src = w + (size_t)e * DM * DH;
#pragma unroll
    for (int i = 0; i < 32; i += 8)
        t[ty + i][tx] = src[(size_t)(d0 + ty + i) * DH + h0 + tx];
    __syncthreads();
#pragma unroll
    for (int i = 0; i < 32; i += 8) {
        float v = t[tx][ty + i];
        size_t o = (size_t)e * DM * DH + (size_t)(h0 + ty + i) * DM + d0 + tx;
        dst[o] = __float2half_rn(v);
    }
}

// ---------------- HMMA GEMM (fp16 2-term split) ----------------
// MODE 1: fused x@w1 / x@w3 + SwiGLU -> g_hh/g_hl (CTA: 128 M x 64 N of each)
// MODE 2: h@w2 -> g_y                (CTA: 128 M x 128 N)
template <int MODE>
__global__ __launch_bounds__(256, 2) void hmma_gemm_kernel() {
    const int e = blockIdx.z;
    int cnt = g_counts[e];
    if (cnt > CAP) cnt = CAP;
    const int m0 = blockIdx.y * BM;
    if (m0 >= cnt) return;
    const int n0 = blockIdx.x * ((MODE == 1) ? 64 : 128);

    extern __shared__ __align__(1024) char smem[];
    uint32_t sb = smem_u32(smem);

    const int tid  = threadIdx.x;
    const int lane = tid & 31;
    const int wid  = tid >> 5;

    // ---- A cp.async mapping: thread t -> row r = t>>1, half = t&1 (hi/lo); 4x16B
    const int r    = tid >> 1;
    const int half = tid & 1;
    const __half* pa;
    if (MODE == 1) {
        int tok = g_tok[e * CAP + m0 + r];
        pa = (half ? g_xlo : g_xhi) + (size_t)tok * DM;
    } else {
        pa = (half ? g_hl : g_hh) + ((size_t)e * CAP + m0 + r) * DH;
    }
    uint32_t soA[4];
#pragma unroll
    for (int j = 0; j < 4; j++)
        soA[j] = sb + swz128((uint32_t)(r * 128 + half * 64 + j * 16));

    // ---- B cp.async mapping: thread t -> row rb = t>>1, 32B chunk cb = t&1; 2x16B
    const int rb = tid >> 1;
    const int cb = tid & 1;
    const __half* pb;
    if (MODE == 1) {
        if (rb < 64) pb = g_w1t + ((size_t)e * DH + n0 + rb) * DM;
        else         pb = g_w3t + ((size_t)e * DH + n0 + rb - 64) * DM;
    } else {
        pb = g_w2t + ((size_t)e * DM + n0 + rb) * DH;
    }
    pb += cb * 16;
    uint32_t soB[2];
#pragma unroll
    for (int j = 0; j < 2; j++)
        soB[j] = sb + 16384 + swz64((uint32_t)(rb * 64 + cb * 32 + j * 16));

    // ---- warp tiling ----
    int wm, wn, mat;
    if (MODE == 1) { wm = wid & 1; wn = (wid >> 1) & 1; mat = wid >> 2; }
    else           { wm = wid & 1; wn = wid >> 1;       mat = 0; }
    const int mbase = wm * 64;
    const int nbB   = (MODE == 1) ? (mat * 64 + wn * 32) : (wn * 32);

    const int lrow = lane & 15;
    const int lkb  = (lane & 16) ? 16 : 0;

    float acc[4][4][4];
#pragma unroll
    for (int mi = 0; mi < 4; mi++)
#pragma unroll
        for (int ni = 0; ni < 4; ni++)
#pragma unroll
            for (int q = 0; q < 4; q++) acc[mi][ni][q] = 0.f;

    // ---- prologue: stages 0..NSTAGE-2 ----
#pragma unroll
    for (int s = 0; s < NSTAGE - 1; s++) {
        int k0 = s * BK;
        uint32_t o = s * STAGE_BYTES;
#pragma unroll
        for (int j = 0; j < 4; j++) cpasync16(soA[j] + o, pa + k0 + j * 8);
#pragma unroll
        for (int j = 0; j < 2; j++) cpasync16(soB[j] + o, pb + k0 + j * 8);
        cp_commit();
    }

    const int bco[4] = {0, 32, 64, 96};   // A chunks: hi-k0, hi-k1, lo-k0, lo-k1

    int stg = 0;                           // stage holding slab kt
    int wst = NSTAGE - 1;                  // stage to write next
    for (int kt = 0; kt < KIT; kt++) {
        cp_wait1();
        __syncthreads();

        {   // issue slab kt + NSTAGE-1
            int ks = kt + NSTAGE - 1;
            if (ks < KIT) {
                int k0 = ks * BK;
                uint32_t o = wst * STAGE_BYTES;
#pragma unroll
                for (int j = 0; j < 4; j++) cpasync16(soA[j] + o, pa + k0 + j * 8);
#pragma unroll
                for (int j = 0; j < 2; j++) cpasync16(soB[j] + o, pb + k0 + j * 8);
            }
            cp_commit();
            wst = (wst == NSTAGE - 1) ? 0 : wst + 1;
        }

        uint32_t aB = sb + stg * STAGE_BYTES;
        uint32_t bB = aB + 16384;
        stg = (stg == NSTAGE - 1) ? 0 : stg + 1;

        // B fragments: 2 k-chunks x 4 n-tiles
        uint32_t bf[2][4][2];
#pragma unroll
        for (int c = 0; c < 2; c++) {
#pragma unroll
            for (int g = 0; g < 2; g++) {
                uint32_t q0, q1, q2, q3;
                uint32_t addr = bB + swz64((uint32_t)((nbB + g * 16 + lrow) * 64 + c * 32 + lkb));
                ldsm4(q0, q1, q2, q3, addr);
                bf[c][g * 2 + 0][0] = q0; bf[c][g * 2 + 0][1] = q2;
                bf[c][g * 2 + 1][0] = q1; bf[c][g * 2 + 1][1] = q3;
            }
        }

        // schedule: Ahi0->B0, Ahi1->B1, Alo0->B0, Alo1->B1  (64 MMAs)
#pragma unroll
        for (int ac = 0; ac < 4; ac++) {
            uint32_t af[4][4];
#pragma unroll
            for (int mi = 0; mi < 4; mi++) {
                uint32_t addr = aB + swz128((uint32_t)((mbase + mi * 16 + lrow) * 128 + bco[ac] + lkb));
                ldsm4(af[mi][0], af[mi][1], af[mi][2], af[mi][3], addr);
            }
            const int bc = ac & 1;
#pragma unroll
            for (int mi = 0; mi < 4; mi++)
#pragma unroll
                for (int ni = 0; ni < 4; ni++)
                    mma16816(acc[mi][ni], af[mi], bf[bc][ni]);
        }
    }

    // ---- epilogue ----
    __syncthreads();
    if (MODE == 1) {
        float* fb = (float*)smem;   // 128 x 64 fp32 = 32KB scratch (reuse stages)
        if (mat == 1) {
#pragma unroll
            for (int mi = 0; mi < 4; mi++)
#pragma unroll
                for (int ni = 0; ni < 4; ni++) {
                    int ml = mbase + mi * 16 + (lane >> 2);
                    int nl = wn * 32 + ni * 8 + 2 * (lane & 3);
                    fb[ml * 64 + nl]           = acc[mi][ni][0];
                    fb[ml * 64 + nl + 1]       = acc[mi][ni][1];
                    fb[(ml + 8) * 64 + nl]     = acc[mi][ni][2];
                    fb[(ml + 8) * 64 + nl + 1] = acc[mi][ni][3];
                }
        }
        __syncthreads();
        if (mat == 0) {
#pragma unroll
            for (int mi = 0; mi < 4; mi++)
#pragma unroll
                for (int ni = 0; ni < 4; ni++) {
                    int ml = mbase + mi * 16 + (lane >> 2);
                    int nl = wn * 32 + ni * 8 + 2 * (lane & 3);
#pragma unroll
                    for (int hrow = 0; hrow < 2; hrow++) {
                        int mloc = ml + hrow * 8;
                        int row  = m0 + mloc;
                        if (row >= cnt) continue;
                        float a10 = acc[mi][ni][2 * hrow + 0];
                        float a11 = acc[mi][ni][2 * hrow + 1];
                        float a30 = fb[mloc * 64 + nl];
                        float a31 = fb[mloc * 64 + nl + 1];
                        float h0 = (a10 / (1.f + __expf(-a10))) * a30;
                        float h1 = (a11 / (1.f + __expf(-a11))) * a31;
                        __half h0h = __float2half_rn(h0);
                        __half h1h = __float2half_rn(h1);
                        __half h0l = __float2half_rn(h0 - __half2float(h0h));
                        __half h1l = __float2half_rn(h1 - __half2float(h1h));
                        uint32_t ph = (uint32_t)__half_as_ushort(h0h) |
                                      ((uint32_t)__half_as_ushort(h1h) << 16);
                        uint32_t pl = (uint32_t)__half_as_ushort(h0l) |
                                      ((uint32_t)__half_as_ushort(h1l) << 16);
                        size_t o = ((size_t)e * CAP + row) * DH + n0 + nl;
                        *(uint32_t*)(g_hh + o) = ph;
                        *(uint32_t*)(g_hl + o) = pl;
                    }
                }
        }
    } else {
#pragma unroll
        for (int mi = 0; mi < 4; mi++)
#pragma unroll
            for (int ni = 0; ni < 4; ni++) {
                int ml = mbase + mi * 16 + (lane >> 2);
                int nl = nbB + ni * 8 + 2 * (lane & 3);
#pragma unroll
                for (int hrow = 0; hrow < 2; hrow++) {
                    int row = m0 + ml + hrow * 8;
                    if (row >= cnt) continue;
                    float2 v = make_float2(acc[mi][ni][2 * hrow], acc[mi][ni][2 * hrow + 1]);
                    *(float2*)(g_y + ((size_t)e * CAP + row) * DM + n0 + nl) = v;
                }
            }
    }
}

// ---------------- combine ----------------
__global__ void combine_kernel(const float* __restrict__ ew, float* __restrict__ out) {
    int i = blockIdx.x * blockDim.x + threadIdx.x;
    int n = i / (DM / 4);
    int c = (i % (DM / 4)) * 4;
    float4 r = make_float4(0.f, 0.f, 0.f, 0.f);
#pragma unroll
    for (int k = 0; k < TOPK; k++) {
        int slot = g_slot[n * TOPK + k];
        if (slot >= 0) {
            float w = ew[n * TOPK + k];
            float4 v = *(const float4*)(g_y + (size_t)slot * DM + c);
            r.x = fmaf(w, v.x, r.x);
            r.y = fmaf(w, v.y, r.y);
            r.z = fmaf(w, v.z, r.z);
            r.w = fmaf(w, v.w, r.w);
        }
    }
    *(float4*)(out + (size_t)n * DM + c) = r;
}

__global__ void counts_kernel(float* __restrict__ out_tail) {
    if (threadIdx.x < NEXP) out_tail[threadIdx.x] = (float)g_counts[threadIdx.x];
}

// ---------------- launch ----------------
extern "C" void kernel_launch(void* const* d_in, const int* in_sizes, int n_in,
                              void* d_out, int out_size) {
    const float* x  = (const float*)d_in[0];
    const float* ew = (const float*)d_in[1];
    const int*   ix = (const int*)  d_in[2];
    const float* w1 = (const float*)d_in[3];
    const float* w2 = (const float*)d_in[4];
    const float* w3 = (const float*)d_in[5];
    float* out = (float*)d_out;

    const int SMEM = NSTAGE * STAGE_BYTES;   // 73728
    cudaFuncSetAttribute(hmma_gemm_kernel<1>, cudaFuncAttributeMaxDynamicSharedMemorySize, SMEM);
    cudaFuncSetAttribute(hmma_gemm_kernel<2>, cudaFuncAttributeMaxDynamicSharedMemorySize, SMEM);

    route_kernel<<<1, 256>>>(ix);
    xsplit_kernel<<<(NTOK * DM) / 256, 256>>>(x);

    dim3 wg(DH / 32, DM / 32, 3 * NEXP);
    dim3 wb(32, 8);
    wprep_kernel<<<wg, wb>>>(w1, w2, w3);

    dim3 g1(DH / 64, CAP / BM, NEXP);    // 32 x 20 x 8
    hmma_gemm_kernel<1><<<g1, 256, SMEM>>>();

    dim3 g2(DM / 128, CAP / BM, NEXP);   // 16 x 20 x 8
    hmma_gemm_kernel<2><<<g2, 256, SMEM>>>();

    combine_kernel<<<(NTOK * (DM / 4)) / 256, 256>>>(ew, out);

    if (out_size >= NTOK * DM + NEXP)
        counts_kernel<<<1, 32>>>(out + (size_t)NTOK * DM);
}